// round 15
// baseline (speedup 1.0000x reference)
#include <cuda_runtime.h>
#include <cstdint>
#include <cstddef>
#include <math.h>

#define BB 16
#define LL 1024
#define DD 128
#define HH 256
#define NSEG 16
#define TWO_PI 6.283185307179586f

typedef unsigned long long u64;
struct __align__(16) ull2 { u64 x, y; };

// Scratch: filtered half-spectrum (planar re/im, conj-symmetric weights folded),
// partial sums, filter params.
__device__ float g_Fre[(size_t)BB * LL * DD];
__device__ float g_Fim[(size_t)BB * LL * DD];
__device__ float g_part[2 * BB * NSEG * DD];
__device__ float g_scale[BB * DD];
__device__ float g_bias[BB * DD];

__device__ __forceinline__ float gelu_exact(float v) {
    return 0.5f * v * (1.0f + erff(v * 0.70710678118654752f));
}

// ---- f32x2 packed helpers (Blackwell FFMA2 path; ptxas won't auto-fuse) ----
__device__ __forceinline__ u64 pack2(float a, float b) {
    u64 r; asm("mov.b64 %0, {%1, %2};" : "=l"(r) : "f"(a), "f"(b)); return r;
}
__device__ __forceinline__ void unpack2(u64 v, float& a, float& b) {
    asm("mov.b64 {%0, %1}, %2;" : "=f"(a), "=f"(b) : "l"(v));
}
__device__ __forceinline__ void ffma2(u64& d, u64 a, u64 b) {
    asm("fma.rn.f32x2 %0, %1, %2, %0;" : "+l"(d) : "l"(a), "l"(b));
}

// ---------------- setup stage 1: partial row-sums of y and z ----------------
__global__ __launch_bounds__(128) void part_kernel(const float* __restrict__ y,
                                                   const float* __restrict__ z)
{
    const int seg = blockIdx.x;
    const int b   = blockIdx.y >> 1;
    const int src = blockIdx.y & 1;
    const int d   = threadIdx.x;
    const float* p = (src ? z : y) + (size_t)b * LL * DD + (size_t)seg * 64 * DD + d;
    float acc = 0.f;
    #pragma unroll 16
    for (int r = 0; r < 64; ++r) acc += p[(size_t)r * DD];
    g_part[((size_t)(src * BB + b) * NSEG + seg) * DD + d] = acc;
}

// ---------------- setup stage 2: the four 128->256->128 MLPs ----------------
__global__ __launch_bounds__(256) void mlp_kernel(
    const int* __restrict__ len_y, const int* __restrict__ len_z,
    const float* __restrict__ W1w1, const float* __restrict__ W1b1,
    const float* __restrict__ W1w2, const float* __restrict__ W1b2,
    const float* __restrict__ B1w1, const float* __restrict__ B1b1,
    const float* __restrict__ B1w2, const float* __restrict__ B1b2,
    const float* __restrict__ W2w1, const float* __restrict__ W2b1,
    const float* __restrict__ W2w2, const float* __restrict__ W2b2,
    const float* __restrict__ B2w1, const float* __restrict__ B2b1,
    const float* __restrict__ B2w2, const float* __restrict__ B2b2)
{
    __shared__ float c1[DD], c2[DD];
    __shared__ float hW1[HH], hB1[HH], hW2[HH], hB2[HH];
    const int b = blockIdx.x;
    const int tid = threadIdx.x;

    if (tid < 128) {
        const int d = tid;
        float s = 0.f;
        #pragma unroll
        for (int seg = 0; seg < NSEG; ++seg)
            s += g_part[((size_t)b * NSEG + seg) * DD + d];
        c1[d] = s / (float)len_y[b];
    } else {
        const int d = tid - 128;
        float s = 0.f;
        #pragma unroll
        for (int seg = 0; seg < NSEG; ++seg)
            s += g_part[((size_t)(BB + b) * NSEG + seg) * DD + d];
        c2[d] = s / (float)len_z[b];
    }
    __syncthreads();

    {
        const int j = tid;
        float a1 = W1b1[j], a2 = B1b1[j], a3 = W2b1[j], a4 = B2b1[j];
        #pragma unroll 8
        for (int d = 0; d < DD; ++d) {
            const float v1 = c1[d], v2 = c2[d];
            a1 += v1 * W1w1[d * HH + j];
            a2 += v1 * B1w1[d * HH + j];
            a3 += v2 * W2w1[d * HH + j];
            a4 += v2 * B2w1[d * HH + j];
        }
        hW1[j] = gelu_exact(a1);
        hB1[j] = gelu_exact(a2);
        hW2[j] = gelu_exact(a3);
        hB2[j] = gelu_exact(a4);
    }
    __syncthreads();

    if (tid < 128) {
        const int d = tid;
        float a1 = W1b2[d], a3 = W2b2[d];
        #pragma unroll 8
        for (int j = 0; j < HH; ++j) {
            a1 += hW1[j] * W1w2[j * DD + d];
            a3 += hW2[j] * W2w2[j * DD + d];
        }
        g_scale[b * DD + d] = 1.0f + 0.5f * (a1 + a3);
    } else {
        const int d = tid - 128;
        float a2 = B1b2[d], a4 = B2b2[d];
        #pragma unroll 8
        for (int j = 0; j < HH; ++j) {
            a2 += hB1[j] * B1w2[j * DD + d];
            a4 += hB2[j] * B2w2[j * DD + d];
        }
        g_bias[b * DD + d] = 0.5f * (a2 + a4);
    }
}

// ---------------- Forward ragged DFT + filter epilogue (half spectrum) -------
// Conjugate symmetry (x real, scale/bias real): only k <= l/2 stored, with
// weight w_k (2 for interior k, 1 for k=0 and k=l/2) folded into the store.
__global__ __launch_bounds__(256) void fwd_kernel(const float* __restrict__ x,
                                                  const int* __restrict__ len_x)
{
    const int b = blockIdx.y;
    const int l = len_x[b];
    const int lhalf = (l >> 1) + 1;      // rows stored: k in [0, l/2]
    const int k0 = blockIdx.x * 32;
    if (k0 >= lhalf) return;

    __shared__ ull2 tw4[LL];
    __shared__ __align__(16) float xs[32][DD];

    const int tid = threadIdx.x;
    const float invl = 1.0f / (float)l;
    for (int m = tid; m < l; m += 256) {
        float s, c;
        sincosf(TWO_PI * (float)m * invl, &s, &c);
        ull2 w; w.x = pack2(c, c); w.y = pack2(-s, -s);
        tw4[m] = w;
    }

    const int g = tid & 31;
    const int kq = tid >> 5;
    int kk[4], mm[4], ks[4];
    #pragma unroll
    for (int i = 0; i < 4; ++i) { kk[i] = k0 + kq * 4 + i; ks[i] = kk[i] % l; mm[i] = 0; }

    u64 ar[4][2] = {}, ai[4][2] = {};   // packed (d,d+1) re / im accumulators

    const float* xb_ = x + (size_t)b * LL * DD;
    float4 pf[4];

#define FWD_LOAD(T0) do {                                                   \
        _Pragma("unroll")                                                   \
        for (int j = 0; j < 4; ++j) {                                       \
            const int f4 = tid + 256 * j;                                   \
            const int r = f4 >> 5, cc = (f4 & 31) * 4;                      \
            const int t = (T0) + r;                                         \
            pf[j] = (t < l) ? *reinterpret_cast<const float4*>(             \
                                  &xb_[(size_t)t * DD + cc])                \
                            : make_float4(0.f, 0.f, 0.f, 0.f);              \
        }                                                                   \
    } while (0)

    FWD_LOAD(0);
    for (int t0 = 0; t0 < l; t0 += 32) {
        #pragma unroll
        for (int j = 0; j < 4; ++j) {
            const int f4 = tid + 256 * j;
            *reinterpret_cast<float4*>(&xs[f4 >> 5][(f4 & 31) * 4]) = pf[j];
        }
        __syncthreads();                 // first iter also covers table build
        if (t0 + 32 < l) FWD_LOAD(t0 + 32);   // LDGs in flight during compute
        #pragma unroll 4
        for (int tt = 0; tt < 32; ++tt) {
            const ull2 xa = *reinterpret_cast<const ull2*>(&xs[tt][g * 4]);
            #pragma unroll
            for (int i = 0; i < 4; ++i) {
                const ull2 w = tw4[mm[i]];
                ffma2(ar[i][0], w.x, xa.x); ffma2(ar[i][1], w.x, xa.y);
                ffma2(ai[i][0], w.y, xa.x); ffma2(ai[i][1], w.y, xa.y);
                mm[i] += ks[i]; if (mm[i] >= l) mm[i] -= l;
            }
        }
        __syncthreads();
    }
#undef FWD_LOAD

    // Epilogue: store w_k * (F*scale + bias); complex-relu is identity.
    const float4 sc = *reinterpret_cast<const float4*>(&g_scale[b * DD + g * 4]);
    const float4 bi = *reinterpret_cast<const float4*>(&g_bias[b * DD + g * 4]);
    #pragma unroll
    for (int i = 0; i < 4; ++i) {
        const int k = kk[i];
        if (k < lhalf) {
            const float w = (k == 0 || 2 * k == l) ? 1.0f : 2.0f;
            float r0, r1, r2, r3, q0, q1, q2, q3;
            unpack2(ar[i][0], r0, r1); unpack2(ar[i][1], r2, r3);
            unpack2(ai[i][0], q0, q1); unpack2(ai[i][1], q2, q3);
            const size_t base = ((size_t)b * LL + k) * DD + g * 4;
            *reinterpret_cast<float4*>(&g_Fre[base]) =
                make_float4((r0*sc.x+bi.x)*w, (r1*sc.y+bi.y)*w,
                            (r2*sc.z+bi.z)*w, (r3*sc.w+bi.w)*w);
            *reinterpret_cast<float4*>(&g_Fim[base]) =
                make_float4(q0*sc.x*w, q1*sc.y*w, q2*sc.z*w, q3*sc.w*w);
        }
    }
}

// ---------------- Inverse ragged DFT (half-spectrum sum, 64-k tiles) --------
// out[b,k,d] = (1/l) * sum_{j<=l/2} [cos*Fre + (-sin)*Fim] (weights pre-folded),
// for k<l; else 0.  Each warp owns 8 k's: data LDS amortized over 2x more FFMA2.
__global__ __launch_bounds__(256) void inv_kernel(float* __restrict__ out,
                                                  const int* __restrict__ len_x)
{
    const int b = blockIdx.y;
    const int l = len_x[b];
    const int lhalf = (l >> 1) + 1;
    const int k0 = blockIdx.x * 64;
    const int tid = threadIdx.x;

    if (k0 >= l) {  // whole tile past l: zero-fill output (buffer is poisoned)
        for (int idx = tid; idx < 64 * DD; idx += 256) {
            const int k = k0 + (idx >> 7);
            out[((size_t)b * LL + k) * DD + (idx & 127)] = 0.f;
        }
        return;
    }

    __shared__ ull2 tw4[LL];
    __shared__ __align__(16) float fre[32][DD];
    __shared__ __align__(16) float fim[32][DD];

    const float invl = 1.0f / (float)l;
    for (int m = tid; m < l; m += 256) {
        float s, c;
        sincosf(TWO_PI * (float)m * invl, &s, &c);
        ull2 w; w.x = pack2(c, c); w.y = pack2(-s, -s);
        tw4[m] = w;
    }

    const int g = tid & 31;
    const int kq = tid >> 5;
    int kk[8], mm[8], ks[8];
    #pragma unroll
    for (int i = 0; i < 8; ++i) { kk[i] = k0 + kq * 8 + i; ks[i] = kk[i] % l; mm[i] = 0; }

    u64 acc[8][2] = {};   // packed (d,d+1) output accumulators

    const float* fre_g = g_Fre + (size_t)b * LL * DD;
    const float* fim_g = g_Fim + (size_t)b * LL * DD;
    float4 pr[4], pi[4];

#define INV_LOAD(T0) do {                                                   \
        _Pragma("unroll")                                                   \
        for (int j = 0; j < 4; ++j) {                                       \
            const int f4 = tid + 256 * j;                                   \
            const int r = f4 >> 5, cc = (f4 & 31) * 4;                      \
            const int t = (T0) + r;                                         \
            if (t < lhalf) {                                                \
                const size_t o = (size_t)t * DD + cc;                       \
                pr[j] = *reinterpret_cast<const float4*>(&fre_g[o]);        \
                pi[j] = *reinterpret_cast<const float4*>(&fim_g[o]);        \
            } else {                                                        \
                pr[j] = make_float4(0.f, 0.f, 0.f, 0.f);                    \
                pi[j] = make_float4(0.f, 0.f, 0.f, 0.f);                    \
            }                                                               \
        }                                                                   \
    } while (0)

    INV_LOAD(0);
    for (int t0 = 0; t0 < lhalf; t0 += 32) {
        #pragma unroll
        for (int j = 0; j < 4; ++j) {
            const int f4 = tid + 256 * j;
            *reinterpret_cast<float4*>(&fre[f4 >> 5][(f4 & 31) * 4]) = pr[j];
            *reinterpret_cast<float4*>(&fim[f4 >> 5][(f4 & 31) * 4]) = pi[j];
        }
        __syncthreads();
        if (t0 + 32 < lhalf) INV_LOAD(t0 + 32);
        #pragma unroll 2
        for (int tt = 0; tt < 32; ++tt) {
            const ull2 fa = *reinterpret_cast<const ull2*>(&fre[tt][g * 4]);
            const ull2 ga = *reinterpret_cast<const ull2*>(&fim[tt][g * 4]);
            #pragma unroll
            for (int i = 0; i < 8; ++i) {
                const ull2 w = tw4[mm[i]];
                ffma2(acc[i][0], w.x, fa.x); ffma2(acc[i][0], w.y, ga.x);
                ffma2(acc[i][1], w.x, fa.y); ffma2(acc[i][1], w.y, ga.y);
                mm[i] += ks[i]; if (mm[i] >= l) mm[i] -= l;
            }
        }
        __syncthreads();
    }
#undef INV_LOAD

    #pragma unroll
    for (int i = 0; i < 8; ++i) {
        const int k = kk[i];
        float o0 = 0.f, o1 = 0.f, o2 = 0.f, o3 = 0.f;
        if (k < l) {
            unpack2(acc[i][0], o0, o1); unpack2(acc[i][1], o2, o3);
            o0 *= invl; o1 *= invl; o2 *= invl; o3 *= invl;
        }
        *reinterpret_cast<float4*>(&out[((size_t)b * LL + k) * DD + g * 4]) =
            make_float4(o0, o1, o2, o3);
    }
}

extern "C" void kernel_launch(void* const* d_in, const int* in_sizes, int n_in,
                              void* d_out, int out_size)
{
    const float* x     = (const float*)d_in[0];
    const float* y     = (const float*)d_in[1];
    const float* z     = (const float*)d_in[2];
    const int*   len_x = (const int*)d_in[3];
    const int*   len_y = (const int*)d_in[4];
    const int*   len_z = (const int*)d_in[5];

    part_kernel<<<dim3(NSEG, 2 * BB), 128>>>(y, z);
    mlp_kernel<<<BB, 256>>>(len_y, len_z,
        (const float*)d_in[6],  (const float*)d_in[7],  (const float*)d_in[8],  (const float*)d_in[9],
        (const float*)d_in[10], (const float*)d_in[11], (const float*)d_in[12], (const float*)d_in[13],
        (const float*)d_in[14], (const float*)d_in[15], (const float*)d_in[16], (const float*)d_in[17],
        (const float*)d_in[18], (const float*)d_in[19], (const float*)d_in[20], (const float*)d_in[21]);

    // fwd: lhalf <= 513 -> at most 17 live 32-k blocks (k0 = 0..512)
    fwd_kernel<<<dim3(17, BB), 256>>>(x, len_x);
    // inv: 64-k tiles cover all k in [0, LL)
    inv_kernel<<<dim3(LL / 64, BB), 256>>>((float*)d_out, len_x);
}